// round 8
// baseline (speedup 1.0000x reference)
#include <cuda_runtime.h>
#include <cuda_bf16.h>
#include <stdint.h>

// ---------------- problem constants ----------------
#define E_TOTAL   1600000
#define N_NODES   100000
#define NODE_DIM  64
#define EDGE_DIM  32
#define HID       128
#define OUT_DIM   64
#define HPRE_DIM  256          // [src-part 128 | tgt-part 128], column-PERMUTED (see below)

#define EPW       8            // edges per warp-tile
#define NTILES    (E_TOTAL / EPW)   // 200000
#define NT2       512
#define NW2       16

// Column permutation: storage position p = 4*l + g  <->  logical j = l + 32*g.
// Applied consistently to g_hpre columns, h smem rows, and W2T k-rows, so each
// lane's quad (LDG.128 / STS.128 at 4*lane) covers j = {lane, lane+32, lane+64, lane+96}
// and all reductions stay order-independent.

// kernel2 smem (floats)
#define W1T_STRIDE 36          // 36 % 32 == 4 -> conflict-free row loads (j = lane+32g)
#define W2T_STRIDE 132         // 132 % 32 == 4 -> conflict-free (o = lane, lane+32)
#define W1T_FLOATS (HID * W1T_STRIDE)          // 4608  (W1T[j][k], k=0..31, j logical)
#define W2T_FLOATS (OUT_DIM * W2T_STRIDE)      // 8448  (W2T[o][p], p permuted k-position)
#define MW_FLOATS  (NW2 * EPW * EDGE_DIM)      // 4096
#define HW_FLOATS  (NW2 * EPW * HID)           // 16384
#define SM2_FLOATS (W1T_FLOATS + W2T_FLOATS + MW_FLOATS + HW_FLOATS)   // 33536
#define SM2_BYTES  (SM2_FLOATS * 4)            // 134144

typedef unsigned long long u64;

__device__ __forceinline__ u64 fma2(u64 a, u64 b, u64 c) {
    u64 d; asm("fma.rn.f32x2 %0, %1, %2, %3;" : "=l"(d) : "l"(a), "l"(b), "l"(c)); return d;
}
__device__ __forceinline__ u64 add2(u64 a, u64 b) {
    u64 d; asm("add.rn.f32x2 %0, %1, %2;" : "=l"(d) : "l"(a), "l"(b)); return d;
}
__device__ __forceinline__ u64 pack2(float lo, float hi) {
    u64 d; asm("mov.b64 %0, {%1, %2};" : "=l"(d) : "f"(lo), "f"(hi)); return d;
}
__device__ __forceinline__ float2 unpack2(u64 v) {
    float2 r; asm("mov.b64 {%0, %1}, %2;" : "=f"(r.x), "=f"(r.y) : "l"(v)); return r;
}

// Per-node precomputed partials, column-permuted:
// position p in [0,128): x[n] @ W1[0:64, j(p)];  p in [128,256): x[n] @ W1[64:128, j(p-128)]
__device__ float g_hpre[(size_t)N_NODES * HPRE_DIM];
__device__ int g_idx_is32;

__global__ void detect_idx_dtype_kernel(const unsigned int* __restrict__ a) {
    unsigned v = 0;
    for (int i = threadIdx.x; i < 2048; i += blockDim.x) v |= a[2 * i + 1];
    int any = __syncthreads_or(v != 0);
    if (threadIdx.x == 0) g_idx_is32 = any ? 1 : 0;
}

// ---------------- kernel 1: per-node precompute (permuted columns) ----------------
__global__ void __launch_bounds__(256, 1)
node_pre_kernel(const float* __restrict__ x, const float* __restrict__ W1)
{
    __shared__ float Wc[64 * 256];   // Wc[k][p], permuted columns
    const int tid = threadIdx.x;
    for (int i = tid; i < 64 * 256; i += 256) {
        int k = i >> 8, p = i & 255;
        int half = p >> 7, pp = p & 127;
        int j = (pp >> 2) + 32 * (pp & 3);
        Wc[i] = W1[(k + half * 64) * HID + j];
    }
    __syncthreads();

    const int warp = tid >> 5, lane = tid & 31;
    const int gw = blockIdx.x * 8 + warp;
    const int nw = gridDim.x * 8;

    for (int n = gw; n < N_NODES; n += nw) {
        u64 acc0 = 0, acc1 = 0, acc2 = 0, acc3 = 0;
        const float4* xr = (const float4*)(x + (size_t)n * NODE_DIM);
#pragma unroll 4
        for (int c = 0; c < 16; c++) {
            float4 m = xr[c];
            float mv[4] = {m.x, m.y, m.z, m.w};
#pragma unroll
            for (int k = 0; k < 4; k++) {
                int kk = 4 * c + k;
                ulonglong2 w0 = *(const ulonglong2*)(Wc + kk * 256 + 4 * lane);
                ulonglong2 w1 = *(const ulonglong2*)(Wc + kk * 256 + 128 + 4 * lane);
                u64 pk = pack2(mv[k], mv[k]);
                acc0 = fma2(pk, w0.x, acc0);
                acc1 = fma2(pk, w0.y, acc1);
                acc2 = fma2(pk, w1.x, acc2);
                acc3 = fma2(pk, w1.y, acc3);
            }
        }
        ulonglong2 s0; s0.x = acc0; s0.y = acc1;
        ulonglong2 s1; s1.x = acc2; s1.y = acc3;
        *(ulonglong2*)(g_hpre + (size_t)n * HPRE_DIM + 4 * lane) = s0;
        *(ulonglong2*)(g_hpre + (size_t)n * HPRE_DIM + 128 + 4 * lane) = s1;
    }
}

// ---------------- kernel 2: per-edge, K-paired f32x2 (zero pack tax) ----------------
__global__ void __launch_bounds__(NT2, 1)
edge_kernel(const float* __restrict__ ea,
            const float* __restrict__ W1,
            const float* __restrict__ b1,
            const float* __restrict__ W2,
            const float* __restrict__ b2,
            const void*  __restrict__ eidx,
            float* __restrict__ out)
{
    extern __shared__ float sm[];
    float* W1T = sm;                     // [128 logical j][36], W1T[j][k] = W1[128+k][j]
    float* W2T = W1T + W1T_FLOATS;       // [64 o][132], W2T[o][p] = W2[j(p)][o]
    float* mwA = W2T + W2T_FLOATS;       // per-warp [8][32] edge_attr
    float* hwA = mwA + MW_FLOATS;        // per-warp [8][128] h (permuted positions)

    const int tid  = threadIdx.x;
    const int warp = tid >> 5;
    const int lane = tid & 31;

    // stage W1 rows 128..159 transposed: W1T[j*36 + k]
    for (int i = tid; i < EDGE_DIM * HID; i += NT2) {
        int k = i >> 7, j = i & 127;
        W1T[j * W1T_STRIDE + k] = W1[(128 + k) * HID + j];
    }
    // stage W2 transposed + k-position permuted: W2T[o*132 + p] = W2[j(p)*64 + o]
    for (int i = tid; i < HID * OUT_DIM; i += NT2) {
        int p = i >> 6, o = i & 63;
        int j = (p >> 2) + 32 * (p & 3);
        W2T[o * W2T_STRIDE + p] = W2[j * OUT_DIM + o];
    }
    __syncthreads();

    const int is32 = g_idx_is32;
    const int* e32 = (const int*)eidx;
    const long long* e64 = (const long long*)eidx;

    float* mw = mwA + warp * (EPW * EDGE_DIM);
    float* hw = hwA + warp * (EPW * HID);

    // bias quads in permuted order (g across quad)
    float b1p[4];
#pragma unroll
    for (int g = 0; g < 4; g++) b1p[g] = b1[lane + 32 * g];
    const float b2v0 = b2[lane];
    const float b2v1 = b2[lane + 32];

    const int gwarp = blockIdx.x * NW2 + warp;
    const int wstride = gridDim.x * NW2;

    for (int t = gwarp; t < NTILES; t += wstride) {
        const int ebase = t * EPW;

        // ---- edge indices: lanes 0..7 load, shfl ----
        int sv = 0, tv = 0;
        if (lane < EPW) {
            int e = ebase + lane;
            if (is32) { sv = e32[e]; tv = e32[E_TOTAL + e]; }
            else      { sv = (int)e64[e]; tv = (int)e64[E_TOTAL + e]; }
        }

        // ---- stage edge_attr (8 x 32 floats, coalesced) ----
#pragma unroll
        for (int pp = 0; pp < 2; pp++) {
            int i = lane + 32 * pp;
            int e = i >> 3, q = i & 7;
            float4 v = *(const float4*)(ea + (size_t)(ebase + e) * EDGE_DIM + 4 * q);
            *(float4*)(mw + e * EDGE_DIM + 4 * q) = v;
        }
        __syncwarp();

        // ---- layer 1 in two half-batches of 4 edges (register pressure) ----
        // acc[e][g]: halves = even/odd-k partials for j = lane + 32*g
#pragma unroll
        for (int hb = 0; hb < 2; hb++) {
            const int e0 = hb * 4;
            u64 acc[4][4];
#pragma unroll
            for (int e = 0; e < 4; e++)
#pragma unroll
                for (int g = 0; g < 4; g++) acc[e][g] = 0ull;

#pragma unroll
            for (int c = 0; c < EDGE_DIM / 4; c++) {       // 8 chunks of 4 k
                ulonglong2 wq[4];
#pragma unroll
                for (int g = 0; g < 4; g++)
                    wq[g] = *(const ulonglong2*)(W1T + (lane + 32 * g) * W1T_STRIDE + 4 * c);
#pragma unroll
                for (int e = 0; e < 4; e++) {
                    ulonglong2 m2 = *(const ulonglong2*)(mw + (e0 + e) * EDGE_DIM + 4 * c);  // broadcast
#pragma unroll
                    for (int g = 0; g < 4; g++) {
                        acc[e][g] = fma2(m2.x, wq[g].x, acc[e][g]);
                        acc[e][g] = fma2(m2.y, wq[g].y, acc[e][g]);
                    }
                }
            }

            // fold + hpre gather + bias + relu + permuted STS.128
#pragma unroll
            for (int e = 0; e < 4; e++) {
                int se = __shfl_sync(0xffffffffu, sv, e0 + e);
                int te = __shfl_sync(0xffffffffu, tv, e0 + e);
                float4 hs = *(const float4*)(g_hpre + (size_t)se * HPRE_DIM + 4 * lane);
                float4 ht = *(const float4*)(g_hpre + (size_t)te * HPRE_DIM + 128 + 4 * lane);
                float2 p0 = unpack2(acc[e][0]);
                float2 p1 = unpack2(acc[e][1]);
                float2 p2 = unpack2(acc[e][2]);
                float2 p3 = unpack2(acc[e][3]);
                float4 hv;
                hv.x = fmaxf(p0.x + p0.y + (hs.x + ht.x + b1p[0]), 0.0f);
                hv.y = fmaxf(p1.x + p1.y + (hs.y + ht.y + b1p[1]), 0.0f);
                hv.z = fmaxf(p2.x + p2.y + (hs.z + ht.z + b1p[2]), 0.0f);
                hv.w = fmaxf(p3.x + p3.y + (hs.w + ht.w + b1p[3]), 0.0f);
                *(float4*)(hw + (e0 + e) * HID + 4 * lane) = hv;   // permuted positions
            }
        }
        __syncwarp();

        // ---- layer 2: o = lane and lane+32; K-paired f32x2 over permuted positions ----
        u64 a2[EPW][2];
#pragma unroll
        for (int e = 0; e < EPW; e++) { a2[e][0] = 0ull; a2[e][1] = 0ull; }

#pragma unroll 4
        for (int c = 0; c < HID / 4; c++) {                // 32 chunks of 4 positions
            ulonglong2 w0 = *(const ulonglong2*)(W2T + lane * W2T_STRIDE + 4 * c);
            ulonglong2 w1 = *(const ulonglong2*)(W2T + (lane + 32) * W2T_STRIDE + 4 * c);
#pragma unroll
            for (int e = 0; e < EPW; e++) {
                ulonglong2 h2 = *(const ulonglong2*)(hw + e * HID + 4 * c);   // broadcast
                a2[e][0] = fma2(h2.x, w0.x, a2[e][0]);
                a2[e][0] = fma2(h2.y, w0.y, a2[e][0]);
                a2[e][1] = fma2(h2.x, w1.x, a2[e][1]);
                a2[e][1] = fma2(h2.y, w1.y, a2[e][1]);
            }
        }

        // ---- fold + bias + coalesced stores ----
#pragma unroll
        for (int e = 0; e < EPW; e++) {
            float2 q0 = unpack2(a2[e][0]);
            float2 q1 = unpack2(a2[e][1]);
            size_t ob = (size_t)(ebase + e) * OUT_DIM;
            out[ob + lane]      = q0.x + q0.y + b2v0;
            out[ob + lane + 32] = q1.x + q1.y + b2v1;
        }
        __syncwarp();   // before mw/hw reuse next tile
    }
}

extern "C" void kernel_launch(void* const* d_in, const int* in_sizes, int n_in,
                              void* d_out, int out_size)
{
    const float* x  = (const float*)d_in[0];
    const float* ea = (const float*)d_in[1];
    const float* W1 = (const float*)d_in[2];
    const float* b1 = (const float*)d_in[3];
    const float* W2 = (const float*)d_in[4];
    const float* b2 = (const float*)d_in[5];
    const void*  ei = d_in[6];
    float* out = (float*)d_out;

    cudaFuncSetAttribute(edge_kernel,
                         cudaFuncAttributeMaxDynamicSharedMemorySize, SM2_BYTES);

    detect_idx_dtype_kernel<<<1, 256>>>((const unsigned int*)ei);
    node_pre_kernel<<<1480, 256>>>(x, W1);
    edge_kernel<<<1480, NT2, SM2_BYTES>>>(ea, W1, b1, W2, b2, ei, out);
}

// round 9
// speedup vs baseline: 1.1634x; 1.1634x over previous
#include <cuda_runtime.h>
#include <cuda_bf16.h>
#include <stdint.h>

// ---------------- problem constants ----------------
#define E_TOTAL   1600000
#define N_NODES   100000
#define NODE_DIM  64
#define EDGE_DIM  32
#define HID       128
#define OUT_DIM   64
#define HPRE_DIM  256          // [src-part 128 | tgt-part 128]

#define EPW       8            // edges per warp-tile (4 edge-pairs)
#define NTILES    (E_TOTAL / EPW)   // 200000
#define NT2       512
#define NW2       16

// ---------------- kernel2 smem byte layout (1024-aligned regions) ----------------
#define SO_W1EA   0                         // [32][128] f32 = 16384
#define SO_W2DUP  16384                     // [64][130] u64 = 66560
#define SO_MDUP   83968                     // 16 warps x [8][32] u64 = 32768
#define SO_HPAIR  116736                    // 16 warps x [4][128] u64 = 65536
#define SO_B2     182272                    // 64 f32
#define SM2_BYTES 182784

#define W2D_STRIDE 130                      // u64 stride; 130*8=1040B == 16B mod 128 -> conflict-free

typedef unsigned long long u64;

__device__ __forceinline__ u64 fma2(u64 a, u64 b, u64 c) {
    u64 d; asm("fma.rn.f32x2 %0, %1, %2, %3;" : "=l"(d) : "l"(a), "l"(b), "l"(c)); return d;
}
__device__ __forceinline__ u64 add2(u64 a, u64 b) {
    u64 d; asm("add.rn.f32x2 %0, %1, %2;" : "=l"(d) : "l"(a), "l"(b)); return d;
}
__device__ __forceinline__ u64 pack2(float lo, float hi) {
    u64 d; asm("mov.b64 %0, {%1, %2};" : "=l"(d) : "f"(lo), "f"(hi)); return d;
}
__device__ __forceinline__ float2 unpack2(u64 v) {
    float2 r; asm("mov.b64 {%0, %1}, %2;" : "=f"(r.x), "=f"(r.y) : "l"(v)); return r;
}

// Per-node precomputed partials (plain column order, as R6):
// [n][0:128] = x[n] @ W1[0:64,:], [n][128:256] = x[n] @ W1[64:128,:]
__device__ float g_hpre[(size_t)N_NODES * HPRE_DIM];
__device__ int g_idx_is32;

__global__ void detect_idx_dtype_kernel(const unsigned int* __restrict__ a) {
    unsigned v = 0;
    for (int i = threadIdx.x; i < 2048; i += blockDim.x) v |= a[2 * i + 1];
    int any = __syncthreads_or(v != 0);
    if (threadIdx.x == 0) g_idx_is32 = any ? 1 : 0;
}

// ---------------- kernel 1: per-node precompute (identical to R6) ----------------
__global__ void __launch_bounds__(256, 1)
node_pre_kernel(const float* __restrict__ x, const float* __restrict__ W1)
{
    __shared__ float Wc[64 * 256];   // Wc[k][j]: j<128 -> W1[k][j], j>=128 -> W1[64+k][j-128]
    const int tid = threadIdx.x;
    for (int i = tid; i < 64 * 256; i += 256) {
        int k = i >> 8, j = i & 255;
        Wc[i] = (j < 128) ? W1[k * HID + j] : W1[(64 + k) * HID + (j - 128)];
    }
    __syncthreads();

    const int warp = tid >> 5, lane = tid & 31;
    const int gw = blockIdx.x * 8 + warp;
    const int nw = gridDim.x * 8;

    for (int n = gw; n < N_NODES; n += nw) {
        u64 acc0 = 0, acc1 = 0, acc2 = 0, acc3 = 0;
        const float4* xr = (const float4*)(x + (size_t)n * NODE_DIM);
#pragma unroll 4
        for (int c = 0; c < 16; c++) {
            float4 m = xr[c];
            float mv[4] = {m.x, m.y, m.z, m.w};
#pragma unroll
            for (int k = 0; k < 4; k++) {
                int kk = 4 * c + k;
                ulonglong2 w0 = *(const ulonglong2*)(Wc + kk * 256 + 4 * lane);
                ulonglong2 w1 = *(const ulonglong2*)(Wc + kk * 256 + 128 + 4 * lane);
                u64 pk = pack2(mv[k], mv[k]);
                acc0 = fma2(pk, w0.x, acc0);
                acc1 = fma2(pk, w0.y, acc1);
                acc2 = fma2(pk, w1.x, acc2);
                acc3 = fma2(pk, w1.y, acc3);
            }
        }
        ulonglong2 s0; s0.x = acc0; s0.y = acc1;
        ulonglong2 s1; s1.x = acc2; s1.y = acc3;
        *(ulonglong2*)(g_hpre + (size_t)n * HPRE_DIM + 4 * lane) = s0;
        *(ulonglong2*)(g_hpre + (size_t)n * HPRE_DIM + 128 + 4 * lane) = s1;
    }
}

// ---------------- kernel 2: per-edge, zero-pack f32x2 via pre-duplicated operands ----------------
__global__ void __launch_bounds__(NT2, 1)
edge_kernel(const float* __restrict__ ea,
            const float* __restrict__ W1,
            const float* __restrict__ b1,
            const float* __restrict__ W2,
            const float* __restrict__ b2,
            const void*  __restrict__ eidx,
            float* __restrict__ out)
{
    extern __shared__ __align__(1024) char smem[];
    float* W1ea = (float*)(smem + SO_W1EA);                       // [32 k][128 j]
    u64*   W2d  = (u64*)(smem + SO_W2DUP);                        // [64 o][130], (w,w)
    float* b2s  = (float*)(smem + SO_B2);

    const int tid  = threadIdx.x;
    const int warp = tid >> 5;
    const int lane = tid & 31;

    u64* mdup  = (u64*)(smem + SO_MDUP) + warp * (EPW * EDGE_DIM);   // [8 e][32 k], (m,m)
    u64* hpair = (u64*)(smem + SO_HPAIR) + warp * (4 * HID);         // [4 ep][128 k], (h_e0,h_e1)

    // ---- stage W1 rows 128..159 as-is ----
    for (int i = tid; i < EDGE_DIM * HID; i += NT2) W1ea[i] = W1[128 * HID + i];
    // ---- stage W2 duplicated: W2d[o][k] = (W2[k][o], W2[k][o]) ----
    for (int i = tid; i < HID * OUT_DIM; i += NT2) {
        int k = i >> 6, o = i & 63;
        float w = W2[i];
        W2d[o * W2D_STRIDE + k] = pack2(w, w);
    }
    for (int i = tid; i < OUT_DIM; i += NT2) b2s[i] = b2[i];
    __syncthreads();

    const int is32 = g_idx_is32;
    const int* e32 = (const int*)eidx;
    const long long* e64 = (const long long*)eidx;

    // biases: j-quad for this lane (acc[e][0] = j {4L,4L+1}, acc[e][1] = j {4L+2,4L+3})
    float4 b1f = *(const float4*)(b1 + 4 * lane);
    const u64 b1q0 = pack2(b1f.x, b1f.y);
    const u64 b1q1 = pack2(b1f.z, b1f.w);
    const float b2v0 = b2s[lane];
    const float b2v1 = b2s[lane + 32];

    const int gwarp = blockIdx.x * NW2 + warp;
    const int wstride = gridDim.x * NW2;

    for (int t = gwarp; t < NTILES; t += wstride) {
        const int ebase = t * EPW;

        // ---- edge indices: lanes 0..7 load, shfl ----
        int sv = 0, tv = 0;
        if (lane < EPW) {
            int e = ebase + lane;
            if (is32) { sv = e32[e]; tv = e32[E_TOTAL + e]; }
            else      { sv = (int)e64[e]; tv = (int)e64[E_TOTAL + e]; }
        }

        // ---- stage edge_attr DUPLICATED: mdup[e][k] = (m,m) ----
#pragma unroll
        for (int p = 0; p < 2; p++) {
            int i = lane + 32 * p;
            int e = i >> 3, q = i & 7;                 // q = float4 index within row
            float4 v = *(const float4*)(ea + (size_t)(ebase + e) * EDGE_DIM + 4 * q);
            ulonglong2 d0, d1;
            d0.x = pack2(v.x, v.x); d0.y = pack2(v.y, v.y);
            d1.x = pack2(v.z, v.z); d1.y = pack2(v.w, v.w);
            *(ulonglong2*)(mdup + e * EDGE_DIM + 4 * q) = d0;        // 32B contiguous/lane
            *(ulonglong2*)(mdup + e * EDGE_DIM + 4 * q + 2) = d1;
        }
        __syncwarp();

        // ---- layer 1 init: b1 + hpre_src + hpre_tgt (j-pairs, no fold needed) ----
        u64 acc[EPW][2];
#pragma unroll
        for (int e = 0; e < EPW; e++) {
            int se = __shfl_sync(0xffffffffu, sv, e);
            int te = __shfl_sync(0xffffffffu, tv, e);
            ulonglong2 hs = *(const ulonglong2*)(g_hpre + (size_t)se * HPRE_DIM + 4 * lane);
            ulonglong2 ht = *(const ulonglong2*)(g_hpre + (size_t)te * HPRE_DIM + 128 + 4 * lane);
            acc[e][0] = add2(add2(b1q0, hs.x), ht.x);
            acc[e][1] = add2(add2(b1q1, hs.y), ht.y);
        }

        // ---- layer 1 GEMM: ea @ W1[128:160,:], zero packs ----
#pragma unroll 2
        for (int c = 0; c < EDGE_DIM / 4; c++) {       // 8 chunks of 4 k
            ulonglong2 wq[4];                           // wq[k] = (W1[k][4L],W1[k][4L+1] | 4L+2,4L+3)
#pragma unroll
            for (int k = 0; k < 4; k++)
                wq[k] = *(const ulonglong2*)(W1ea + (4 * c + k) * HID + 4 * lane);
#pragma unroll
            for (int e = 0; e < EPW; e++) {
                ulonglong2 m0 = *(const ulonglong2*)(mdup + e * EDGE_DIM + 4 * c);      // k=4c,4c+1
                ulonglong2 m1 = *(const ulonglong2*)(mdup + e * EDGE_DIM + 4 * c + 2);  // k=4c+2,4c+3
                acc[e][0] = fma2(m0.x, wq[0].x, acc[e][0]);
                acc[e][1] = fma2(m0.x, wq[0].y, acc[e][1]);
                acc[e][0] = fma2(m0.y, wq[1].x, acc[e][0]);
                acc[e][1] = fma2(m0.y, wq[1].y, acc[e][1]);
                acc[e][0] = fma2(m1.x, wq[2].x, acc[e][0]);
                acc[e][1] = fma2(m1.x, wq[2].y, acc[e][1]);
                acc[e][0] = fma2(m1.y, wq[3].x, acc[e][0]);
                acc[e][1] = fma2(m1.y, wq[3].y, acc[e][1]);
            }
        }

        // ---- layer 1 epilogue: relu + EDGE-PAIR into hpair[ep][k] ----
#pragma unroll
        for (int ep = 0; ep < 4; ep++) {
            float2 a00 = unpack2(acc[2 * ep][0]);      // e0: j=4L,4L+1
            float2 a01 = unpack2(acc[2 * ep][1]);      // e0: j=4L+2,4L+3
            float2 a10 = unpack2(acc[2 * ep + 1][0]);  // e1
            float2 a11 = unpack2(acc[2 * ep + 1][1]);
            ulonglong2 s0, s1;
            s0.x = pack2(fmaxf(a00.x, 0.0f), fmaxf(a10.x, 0.0f));   // k=4L
            s0.y = pack2(fmaxf(a00.y, 0.0f), fmaxf(a10.y, 0.0f));   // k=4L+1
            s1.x = pack2(fmaxf(a01.x, 0.0f), fmaxf(a11.x, 0.0f));   // k=4L+2
            s1.y = pack2(fmaxf(a01.y, 0.0f), fmaxf(a11.y, 0.0f));   // k=4L+3
            *(ulonglong2*)(hpair + ep * HID + 4 * lane) = s0;       // 32B contiguous/lane
            *(ulonglong2*)(hpair + ep * HID + 4 * lane + 2) = s1;
        }
        __syncwarp();

        // ---- layer 2: h @ W2, edge-paired halves, zero packs ----
        u64 ap[4][2];
#pragma unroll
        for (int ep = 0; ep < 4; ep++) { ap[ep][0] = 0ull; ap[ep][1] = 0ull; }

#pragma unroll 4
        for (int c = 0; c < HID / 4; c++) {            // 32 chunks of 4 k
            ulonglong2 w0a = *(const ulonglong2*)(W2d + lane * W2D_STRIDE + 4 * c);          // o=lane
            ulonglong2 w0b = *(const ulonglong2*)(W2d + lane * W2D_STRIDE + 4 * c + 2);
            ulonglong2 w1a = *(const ulonglong2*)(W2d + (lane + 32) * W2D_STRIDE + 4 * c);   // o=lane+32
            ulonglong2 w1b = *(const ulonglong2*)(W2d + (lane + 32) * W2D_STRIDE + 4 * c + 2);
#pragma unroll
            for (int ep = 0; ep < 4; ep++) {
                ulonglong2 h0 = *(const ulonglong2*)(hpair + ep * HID + 4 * c);      // broadcast
                ulonglong2 h1 = *(const ulonglong2*)(hpair + ep * HID + 4 * c + 2);
                ap[ep][0] = fma2(h0.x, w0a.x, ap[ep][0]);
                ap[ep][0] = fma2(h0.y, w0a.y, ap[ep][0]);
                ap[ep][0] = fma2(h1.x, w0b.x, ap[ep][0]);
                ap[ep][0] = fma2(h1.y, w0b.y, ap[ep][0]);
                ap[ep][1] = fma2(h0.x, w1a.x, ap[ep][1]);
                ap[ep][1] = fma2(h0.y, w1a.y, ap[ep][1]);
                ap[ep][1] = fma2(h1.x, w1b.x, ap[ep][1]);
                ap[ep][1] = fma2(h1.y, w1b.y, ap[ep][1]);
            }
        }

        // ---- layer 2 epilogue: halves are edges, add bias, store ----
#pragma unroll
        for (int ep = 0; ep < 4; ep++) {
            float2 p0 = unpack2(ap[ep][0]);            // (e0, e1) at o = lane
            float2 p1 = unpack2(ap[ep][1]);            // (e0, e1) at o = lane+32
            size_t ob0 = (size_t)(ebase + 2 * ep) * OUT_DIM;
            size_t ob1 = (size_t)(ebase + 2 * ep + 1) * OUT_DIM;
            out[ob0 + lane]      = p0.x + b2v0;
            out[ob1 + lane]      = p0.y + b2v0;
            out[ob0 + lane + 32] = p1.x + b2v1;
            out[ob1 + lane + 32] = p1.y + b2v1;
        }
        __syncwarp();   // before mdup/hpair reuse next tile
    }
}

extern "C" void kernel_launch(void* const* d_in, const int* in_sizes, int n_in,
                              void* d_out, int out_size)
{
    const float* x  = (const float*)d_in[0];
    const float* ea = (const float*)d_in[1];
    const float* W1 = (const float*)d_in[2];
    const float* b1 = (const float*)d_in[3];
    const float* W2 = (const float*)d_in[4];
    const float* b2 = (const float*)d_in[5];
    const void*  ei = d_in[6];
    float* out = (float*)d_out;

    cudaFuncSetAttribute(edge_kernel,
                         cudaFuncAttributeMaxDynamicSharedMemorySize, SM2_BYTES);

    detect_idx_dtype_kernel<<<1, 256>>>((const unsigned int*)ei);
    node_pre_kernel<<<1480, 256>>>(x, W1);
    edge_kernel<<<1480, NT2, SM2_BYTES>>>(ea, W1, b1, W2, b2, ei, out);
}

// round 11
// speedup vs baseline: 1.3023x; 1.1194x over previous
#include <cuda_runtime.h>
#include <cuda_bf16.h>
#include <stdint.h>

// ---------------- problem constants ----------------
#define E_TOTAL   1600000
#define N_NODES   100000
#define NODE_DIM  64
#define EDGE_DIM  32
#define HID       128
#define OUT_DIM   64
#define HPRE_DIM  256          // [src-part 128 | tgt-part 128]

#define EPW       8            // edges per warp-tile
#define NTILES    (E_TOTAL / EPW)   // 200000
#define NT2       512
#define NW2       16

// ---------------- kernel2 smem byte layout ----------------
#define SO_W1EA   0                         // [32 k][128 j] f32        = 16384
#define SO_W2T    16384                     // [64 o][132] f32          = 33792
#define SO_MDUP   50176                     // 16 warps x [8 e][32 k] u64 = 32768
#define SO_HW     82944                     // 16 warps x [8 e][128 j] f32 = 65536
#define SO_B2     148480                    // 64 f32
#define SM2_BYTES 148736

#define W2T_STRIDE 132                      // f32 stride; 132 % 32 == 4 -> conflict-free LDS.128

typedef unsigned long long u64;

__device__ __forceinline__ u64 fma2(u64 a, u64 b, u64 c) {
    u64 d; asm("fma.rn.f32x2 %0, %1, %2, %3;" : "=l"(d) : "l"(a), "l"(b), "l"(c)); return d;
}
__device__ __forceinline__ u64 add2(u64 a, u64 b) {
    u64 d; asm("add.rn.f32x2 %0, %1, %2;" : "=l"(d) : "l"(a), "l"(b)); return d;
}
__device__ __forceinline__ u64 pack2(float lo, float hi) {
    u64 d; asm("mov.b64 %0, {%1, %2};" : "=l"(d) : "f"(lo), "f"(hi)); return d;
}
__device__ __forceinline__ float2 unpack2(u64 v) {
    float2 r; asm("mov.b64 {%0, %1}, %2;" : "=f"(r.x), "=f"(r.y) : "l"(v)); return r;
}

// Per-node precomputed partials:
// [n][0:128] = x[n] @ W1[0:64,:], [n][128:256] = x[n] @ W1[64:128,:]
__device__ float g_hpre[(size_t)N_NODES * HPRE_DIM];
__device__ int g_idx_is32;

__global__ void detect_idx_dtype_kernel(const unsigned int* __restrict__ a) {
    unsigned v = 0;
    for (int i = threadIdx.x; i < 2048; i += blockDim.x) v |= a[2 * i + 1];
    int any = __syncthreads_or(v != 0);
    if (threadIdx.x == 0) g_idx_is32 = any ? 1 : 0;
}

// ---------------- kernel 1: per-node precompute (unchanged, proven) ----------------
__global__ void __launch_bounds__(256, 1)
node_pre_kernel(const float* __restrict__ x, const float* __restrict__ W1)
{
    __shared__ float Wc[64 * 256];   // Wc[k][j]: j<128 -> W1[k][j], j>=128 -> W1[64+k][j-128]
    const int tid = threadIdx.x;
    for (int i = tid; i < 64 * 256; i += 256) {
        int k = i >> 8, j = i & 255;
        Wc[i] = (j < 128) ? W1[k * HID + j] : W1[(64 + k) * HID + (j - 128)];
    }
    __syncthreads();

    const int warp = tid >> 5, lane = tid & 31;
    const int gw = blockIdx.x * 8 + warp;
    const int nw = gridDim.x * 8;

    for (int n = gw; n < N_NODES; n += nw) {
        u64 acc0 = 0, acc1 = 0, acc2 = 0, acc3 = 0;
        const float4* xr = (const float4*)(x + (size_t)n * NODE_DIM);
#pragma unroll 4
        for (int c = 0; c < 16; c++) {
            float4 m = xr[c];
            float mv[4] = {m.x, m.y, m.z, m.w};
#pragma unroll
            for (int k = 0; k < 4; k++) {
                int kk = 4 * c + k;
                ulonglong2 w0 = *(const ulonglong2*)(Wc + kk * 256 + 4 * lane);
                ulonglong2 w1 = *(const ulonglong2*)(Wc + kk * 256 + 128 + 4 * lane);
                u64 pk = pack2(mv[k], mv[k]);
                acc0 = fma2(pk, w0.x, acc0);
                acc1 = fma2(pk, w0.y, acc1);
                acc2 = fma2(pk, w1.x, acc2);
                acc3 = fma2(pk, w1.y, acc3);
            }
        }
        ulonglong2 s0; s0.x = acc0; s0.y = acc1;
        ulonglong2 s1; s1.x = acc2; s1.y = acc3;
        *(ulonglong2*)(g_hpre + (size_t)n * HPRE_DIM + 4 * lane) = s0;
        *(ulonglong2*)(g_hpre + (size_t)n * HPRE_DIM + 128 + 4 * lane) = s1;
    }
}

// ---------------- kernel 2: zero-pack layer1 (j-paired) + zero-pack layer2 (K-paired) ----------------
__global__ void __launch_bounds__(NT2, 1)
edge_kernel(const float* __restrict__ ea,
            const float* __restrict__ W1,
            const float* __restrict__ b1,
            const float* __restrict__ W2,
            const float* __restrict__ b2,
            const void*  __restrict__ eidx,
            float* __restrict__ out)
{
    extern __shared__ __align__(1024) char smem[];
    float* W1ea = (float*)(smem + SO_W1EA);      // [32 k][128 j]
    float* W2T  = (float*)(smem + SO_W2T);       // [64 o][132], W2T[o][k] = W2[k][o]
    float* b2s  = (float*)(smem + SO_B2);

    const int tid  = threadIdx.x;
    const int warp = tid >> 5;
    const int lane = tid & 31;

    u64*   mdup = (u64*)(smem + SO_MDUP) + warp * (EPW * EDGE_DIM);   // [8 e][32 k], (m,m)
    float* hw   = (float*)(smem + SO_HW) + warp * (EPW * HID);        // [8 e][128 j] plain

    // ---- stage W1 rows 128..159 as-is ----
    for (int i = tid; i < EDGE_DIM * HID; i += NT2) W1ea[i] = W1[128 * HID + i];
    // ---- stage W2 transposed: W2T[o][k] = W2[k][o] ----
    for (int i = tid; i < HID * OUT_DIM; i += NT2) {
        int k = i >> 6, o = i & 63;
        W2T[o * W2T_STRIDE + k] = W2[i];
    }
    for (int i = tid; i < OUT_DIM; i += NT2) b2s[i] = b2[i];
    __syncthreads();

    const int is32 = g_idx_is32;
    const int* e32 = (const int*)eidx;
    const long long* e64 = (const long long*)eidx;

    // biases: j-quad for this lane (acc[e][0] = j {4L,4L+1}, acc[e][1] = j {4L+2,4L+3})
    float4 b1f = *(const float4*)(b1 + 4 * lane);
    const u64 b1q0 = pack2(b1f.x, b1f.y);
    const u64 b1q1 = pack2(b1f.z, b1f.w);
    const float b2v0 = b2s[lane];
    const float b2v1 = b2s[lane + 32];

    const int gwarp = blockIdx.x * NW2 + warp;
    const int wstride = gridDim.x * NW2;

    for (int t = gwarp; t < NTILES; t += wstride) {
        const int ebase = t * EPW;

        // ---- edge indices: lanes 0..7 load, shfl ----
        int sv = 0, tv = 0;
        if (lane < EPW) {
            int e = ebase + lane;
            if (is32) { sv = e32[e]; tv = e32[E_TOTAL + e]; }
            else      { sv = (int)e64[e]; tv = (int)e64[E_TOTAL + e]; }
        }

        // ---- stage edge_attr DUPLICATED: mdup[e][k] = (m,m) ----
#pragma unroll
        for (int p = 0; p < 2; p++) {
            int i = lane + 32 * p;
            int e = i >> 3, q = i & 7;
            float4 v = *(const float4*)(ea + (size_t)(ebase + e) * EDGE_DIM + 4 * q);
            ulonglong2 d0, d1;
            d0.x = pack2(v.x, v.x); d0.y = pack2(v.y, v.y);
            d1.x = pack2(v.z, v.z); d1.y = pack2(v.w, v.w);
            *(ulonglong2*)(mdup + e * EDGE_DIM + 4 * q) = d0;
            *(ulonglong2*)(mdup + e * EDGE_DIM + 4 * q + 2) = d1;
        }
        __syncwarp();

        // ---- layer 1 init: b1 + hpre_src + hpre_tgt (j-pairs, zero packs) ----
        u64 acc[EPW][2];
#pragma unroll
        for (int e = 0; e < EPW; e++) {
            int se = __shfl_sync(0xffffffffu, sv, e);
            int te = __shfl_sync(0xffffffffu, tv, e);
            ulonglong2 hs = *(const ulonglong2*)(g_hpre + (size_t)se * HPRE_DIM + 4 * lane);
            ulonglong2 ht = *(const ulonglong2*)(g_hpre + (size_t)te * HPRE_DIM + 128 + 4 * lane);
            acc[e][0] = add2(add2(b1q0, hs.x), ht.x);
            acc[e][1] = add2(add2(b1q1, hs.y), ht.y);
        }

        // ---- layer 1 GEMM: ea @ W1[128:160,:], zero packs (R9-proven form) ----
#pragma unroll 2
        for (int c = 0; c < EDGE_DIM / 4; c++) {       // 8 chunks of 4 k
            ulonglong2 wq[4];                           // wq[k] = W1[k][4L..4L+3] as 2 j-pairs
#pragma unroll
            for (int k = 0; k < 4; k++)
                wq[k] = *(const ulonglong2*)(W1ea + (4 * c + k) * HID + 4 * lane);
#pragma unroll
            for (int e = 0; e < EPW; e++) {
                ulonglong2 m0 = *(const ulonglong2*)(mdup + e * EDGE_DIM + 4 * c);      // k=4c,4c+1
                ulonglong2 m1 = *(const ulonglong2*)(mdup + e * EDGE_DIM + 4 * c + 2);  // k=4c+2,4c+3
                acc[e][0] = fma2(m0.x, wq[0].x, acc[e][0]);
                acc[e][1] = fma2(m0.x, wq[0].y, acc[e][1]);
                acc[e][0] = fma2(m0.y, wq[1].x, acc[e][0]);
                acc[e][1] = fma2(m0.y, wq[1].y, acc[e][1]);
                acc[e][0] = fma2(m1.x, wq[2].x, acc[e][0]);
                acc[e][1] = fma2(m1.x, wq[2].y, acc[e][1]);
                acc[e][0] = fma2(m1.y, wq[3].x, acc[e][0]);
                acc[e][1] = fma2(m1.y, wq[3].y, acc[e][1]);
            }
        }

        // ---- layer 1 epilogue: relu + plain f32 j-quad store (STS.128, conflict-free) ----
#pragma unroll
        for (int e = 0; e < EPW; e++) {
            float2 p0 = unpack2(acc[e][0]);
            float2 p1 = unpack2(acc[e][1]);
            float4 hv;
            hv.x = fmaxf(p0.x, 0.0f); hv.y = fmaxf(p0.y, 0.0f);
            hv.z = fmaxf(p1.x, 0.0f); hv.w = fmaxf(p1.y, 0.0f);
            *(float4*)(hw + e * HID + 4 * lane) = hv;
        }
        __syncwarp();

        // ---- layer 2: K-paired f32x2, zero packs, plain weights (R8-proven form) ----
        // lane covers o = lane and lane+32; acc halves = k-parity partials.
        u64 a2[EPW][2];
#pragma unroll
        for (int e = 0; e < EPW; e++) { a2[e][0] = 0ull; a2[e][1] = 0ull; }

#pragma unroll 4
        for (int c = 0; c < HID / 4; c++) {            // 32 chunks of 4 k
            ulonglong2 w0 = *(const ulonglong2*)(W2T + lane * W2T_STRIDE + 4 * c);
            ulonglong2 w1 = *(const ulonglong2*)(W2T + (lane + 32) * W2T_STRIDE + 4 * c);
#pragma unroll
            for (int e = 0; e < EPW; e++) {
                ulonglong2 h2 = *(const ulonglong2*)(hw + e * HID + 4 * c);   // broadcast, k 4c..4c+3
                a2[e][0] = fma2(h2.x, w0.x, a2[e][0]);
                a2[e][0] = fma2(h2.y, w0.y, a2[e][0]);
                a2[e][1] = fma2(h2.x, w1.x, a2[e][1]);
                a2[e][1] = fma2(h2.y, w1.y, a2[e][1]);
            }
        }

        // ---- fold k-parity halves + bias + coalesced stores ----
#pragma unroll
        for (int e = 0; e < EPW; e++) {
            float2 q0 = unpack2(a2[e][0]);
            float2 q1 = unpack2(a2[e][1]);
            size_t ob = (size_t)(ebase + e) * OUT_DIM;
            out[ob + lane]      = q0.x + q0.y + b2v0;
            out[ob + lane + 32] = q1.x + q1.y + b2v1;
        }
        __syncwarp();   // before mdup/hw reuse next tile
    }
}

extern "C" void kernel_launch(void* const* d_in, const int* in_sizes, int n_in,
                              void* d_out, int out_size)
{
    const float* x  = (const float*)d_in[0];
    const float* ea = (const float*)d_in[1];
    const float* W1 = (const float*)d_in[2];
    const float* b1 = (const float*)d_in[3];
    const float* W2 = (const float*)d_in[4];
    const float* b2 = (const float*)d_in[5];
    const void*  ei = d_in[6];
    float* out = (float*)d_out;

    cudaFuncSetAttribute(edge_kernel,
                         cudaFuncAttributeMaxDynamicSharedMemorySize, SM2_BYTES);

    detect_idx_dtype_kernel<<<1, 256>>>((const unsigned int*)ei);
    node_pre_kernel<<<1472, 256>>>(x, W1);
    edge_kernel<<<1472, NT2, SM2_BYTES>>>(ea, W1, b1, W2, b2, ei, out);
}